// round 3
// baseline (speedup 1.0000x reference)
#include <cuda_runtime.h>

// HMM batched log-forward, scaled linear-domain formulation.
// B=128 sequences, S=65 states (state 0 = bookend, dropped from recursion),
// V=1024 observation vocab, T=8192 timesteps.
//
// Inputs (metadata order):
//   d_in[0] log_trans  [65*65]  float32
//   d_in[1] log_emit   [65*1024] float32
//   d_in[2] log_pi     [65]     float32 (delta on state 0; exploited analytically)
//   d_in[3] obvs       [128*8192] int32
// Output: float32 [128] log-evidence per sequence.

#define BB 128
#define SS 65
#define NS 64    // active states 1..64
#define VV 1024

// Transposed, exponentiated emission table: g_emitT[o*64 + j] = exp(log_emit[(j+1), o])
__device__ float g_emitT[VV * NS];

__global__ void build_emitT_kernel(const float* __restrict__ log_emit) {
    int idx = blockIdx.x * blockDim.x + threadIdx.x;
    if (idx >= VV * NS) return;
    int o = idx >> 6;        // observation symbol
    int j = idx & 63;        // active state index (state j+1)
    g_emitT[idx] = __expf(log_emit[(j + 1) * VV + o]);
}

__global__ __launch_bounds__(NS, 1) void hmm_forward_kernel(
    const float* __restrict__ log_trans,
    const int*   __restrict__ obvs,
    float*       __restrict__ out,
    int T)
{
    const int b = blockIdx.x;
    const int j = threadIdx.x;            // dest state j+1
    const int lane = j & 31;
    const int wid  = j >> 5;
    const int* __restrict__ orow = obvs + (long long)b * T;

    __shared__ float4 ubuf4[2][NS / 4];   // double-buffered scaled alpha vector
    __shared__ float  red[2];             // cross-warp reduction scratch

    // ---- Load transition column into registers (linear domain), once ----
    float Tcol[NS];
    #pragma unroll
    for (int i = 0; i < NS; i++)
        Tcol[i] = __expf(log_trans[(i + 1) * SS + (j + 1)]);

    // ---- t = 0: pi is a delta on state 0 -> u1[j] = exp(LT[0,j+1]) * em0[j] ----
    int o0 = orow[0];
    float v = __expf(log_trans[0 * SS + (j + 1)]) * g_emitT[o0 * NS + j];

    float Lacc = 0.f, Lc = 0.f;           // Kahan accumulator for sum of log Z

    // Prefetch pipeline: em_next = emission row for step t (at loop top),
    //                    onext   = obvs[t+1]
    float em_next = g_emitT[orow[1] * NS + j];
    int   onext   = orow[2];

    for (int t = 1; t < T; t++) {
        const int buf = t & 1;
        reinterpret_cast<float*>(ubuf4[buf])[j] = v;
        __syncthreads();

        const float em = em_next;
        // Prefetch next step's emission + obs (clamped indices keep loads valid)
        float em_p = g_emitT[onext * NS + j];
        int   on_p = orow[(t + 2 < T) ? (t + 2) : (T - 1)];

        // 64-wide dot: d_j = sum_i u_i * T[i][j], fully unrolled, 4 accumulators
        float acc0 = 0.f, acc1 = 0.f, acc2 = 0.f, acc3 = 0.f;
        const float4* __restrict__ u4 = ubuf4[buf];
        #pragma unroll
        for (int i = 0; i < NS / 4; i++) {
            float4 uu = u4[i];
            acc0 = fmaf(uu.x, Tcol[4 * i + 0], acc0);
            acc1 = fmaf(uu.y, Tcol[4 * i + 1], acc1);
            acc2 = fmaf(uu.z, Tcol[4 * i + 2], acc2);
            acc3 = fmaf(uu.w, Tcol[4 * i + 3], acc3);
        }
        v = ((acc0 + acc1) + (acc2 + acc3)) * em;

        em_next = em_p;
        onext   = on_p;

        // ---- Renormalize every 8 steps: u /= sum(u), Lacc += log(sum) ----
        if ((t & 7) == 7) {
            float z = v;
            #pragma unroll
            for (int s2 = 16; s2 > 0; s2 >>= 1)
                z += __shfl_xor_sync(0xffffffffu, z, s2);
            if (lane == 0) red[wid] = z;
            __syncthreads();
            const float Z = red[0] + red[1];
            v *= __frcp_rn(Z);
            const float lz = __logf(Z);
            // Kahan summation
            const float y = lz - Lc;
            const float s = Lacc + y;
            Lc = (s - Lacc) - y;
            Lacc = s;
        }
    }

    // ---- Termination: logL = Lacc + logsumexp_j( log(v_j) + LT[j+1, 0] ) ----
    const float lt0 = log_trans[(j + 1) * SS + 0];
    float a = (v > 0.f) ? (__logf(v) + lt0) : -3.0e38f;

    float m = a;
    #pragma unroll
    for (int s2 = 16; s2 > 0; s2 >>= 1)
        m = fmaxf(m, __shfl_xor_sync(0xffffffffu, m, s2));
    __syncthreads();                       // protect red[] WAR vs renorm reads
    if (lane == 0) red[wid] = m;
    __syncthreads();
    m = fmaxf(red[0], red[1]);

    float e = __expf(a - m);
    #pragma unroll
    for (int s2 = 16; s2 > 0; s2 >>= 1)
        e += __shfl_xor_sync(0xffffffffu, e, s2);
    __syncthreads();                       // protect red[] WAR vs max reads
    if (lane == 0) red[wid] = e;
    __syncthreads();

    if (j == 0) {
        const float E = red[0] + red[1];
        out[b] = Lacc + m + __logf(E);
    }
}

extern "C" void kernel_launch(void* const* d_in, const int* in_sizes, int n_in,
                              void* d_out, int out_size) {
    const float* log_trans = (const float*)d_in[0];
    const float* log_emit  = (const float*)d_in[1];
    // d_in[2] (log_pi) is a delta on state 0 by construction; handled analytically.
    const int*   obvs      = (const int*)d_in[3];
    float*       out       = (float*)d_out;

    const int T = in_sizes[3] / BB;

    build_emitT_kernel<<<(VV * NS + 255) / 256, 256>>>(log_emit);
    hmm_forward_kernel<<<BB, NS>>>(log_trans, obvs, out, T);
}

// round 4
// speedup vs baseline: 1.0469x; 1.0469x over previous
#include <cuda_runtime.h>

// HMM batched log-forward, scaled linear-domain formulation.
// B=128 sequences, S=65 states (state 0 = bookend, dropped from recursion),
// V=1024 observation vocab, T=8192 timesteps.
//
// Inputs (metadata order):
//   d_in[0] log_trans  [65*65]  float32
//   d_in[1] log_emit   [65*1024] float32
//   d_in[2] log_pi     [65]     float32 (delta on state 0; exploited analytically)
//   d_in[3] obvs       [128*8192] int32
// Output: float32 [128] log-evidence per sequence.

#define BB 128
#define SS 65
#define NS 64    // active states 1..64
#define VV 1024

// Transposed, exponentiated emission table: g_emitT[o*64 + j] = exp(log_emit[(j+1), o])
__device__ float g_emitT[VV * NS];

__global__ void build_emitT_kernel(const float* __restrict__ log_emit) {
    int idx = blockIdx.x * blockDim.x + threadIdx.x;
    if (idx >= VV * NS) return;
    int o = idx >> 6;        // observation symbol
    int j = idx & 63;        // active state index (state j+1)
    g_emitT[idx] = __expf(log_emit[(j + 1) * VV + o]);
}

__global__ __launch_bounds__(NS, 1) void hmm_forward_kernel(
    const float* __restrict__ log_trans,
    const int*   __restrict__ obvs,
    float*       __restrict__ out,
    int T)
{
    const int b = blockIdx.x;
    const int j = threadIdx.x;            // dest state j+1
    const int lane = j & 31;
    const int wid  = j >> 5;
    const int* __restrict__ orow = obvs + (long long)b * T;

    __shared__ float4 ubuf4[2][NS / 4];   // double-buffered scaled alpha vector
    __shared__ float  red[2];             // cross-warp reduction scratch

    // ---- Load transition column into registers (linear domain), once ----
    float Tcol[NS];
    #pragma unroll
    for (int i = 0; i < NS; i++)
        Tcol[i] = __expf(log_trans[(i + 1) * SS + (j + 1)]);

    // ---- t = 0: pi is a delta on state 0 -> u1[j] = exp(LT[0,j+1]) * em0[j] ----
    int o0 = orow[0];
    float v = __expf(log_trans[0 * SS + (j + 1)]) * g_emitT[o0 * NS + j];

    float Lacc = 0.f, Lc = 0.f;           // Kahan accumulator for sum of log Z

    // Prefetch pipeline: em_next = emission row for step t (at loop top),
    //                    onext   = obvs[t+1]
    float em_next = g_emitT[orow[1] * NS + j];
    int   onext   = orow[2];

    for (int t = 1; t < T; t++) {
        const int buf = t & 1;
        reinterpret_cast<float*>(ubuf4[buf])[j] = v;
        __syncthreads();

        const float em = em_next;
        // Prefetch next step's emission + obs (clamped indices keep loads valid)
        float em_p = g_emitT[onext * NS + j];
        int   on_p = orow[(t + 2 < T) ? (t + 2) : (T - 1)];

        // 64-wide dot: d_j = sum_i u_i * T[i][j], fully unrolled, 4 accumulators
        float acc0 = 0.f, acc1 = 0.f, acc2 = 0.f, acc3 = 0.f;
        const float4* __restrict__ u4 = ubuf4[buf];
        #pragma unroll
        for (int i = 0; i < NS / 4; i++) {
            float4 uu = u4[i];
            acc0 = fmaf(uu.x, Tcol[4 * i + 0], acc0);
            acc1 = fmaf(uu.y, Tcol[4 * i + 1], acc1);
            acc2 = fmaf(uu.z, Tcol[4 * i + 2], acc2);
            acc3 = fmaf(uu.w, Tcol[4 * i + 3], acc3);
        }
        v = ((acc0 + acc1) + (acc2 + acc3)) * em;

        em_next = em_p;
        onext   = on_p;

        // ---- Renormalize every 8 steps: u /= sum(u), Lacc += log(sum) ----
        if ((t & 7) == 7) {
            float z = v;
            #pragma unroll
            for (int s2 = 16; s2 > 0; s2 >>= 1)
                z += __shfl_xor_sync(0xffffffffu, z, s2);
            if (lane == 0) red[wid] = z;
            __syncthreads();
            const float Z = red[0] + red[1];
            v *= __frcp_rn(Z);
            const float lz = __logf(Z);
            // Kahan summation
            const float y = lz - Lc;
            const float s = Lacc + y;
            Lc = (s - Lacc) - y;
            Lacc = s;
        }
    }

    // ---- Termination: logL = Lacc + logsumexp_j( log(v_j) + LT[j+1, 0] ) ----
    const float lt0 = log_trans[(j + 1) * SS + 0];
    float a = (v > 0.f) ? (__logf(v) + lt0) : -3.0e38f;

    float m = a;
    #pragma unroll
    for (int s2 = 16; s2 > 0; s2 >>= 1)
        m = fmaxf(m, __shfl_xor_sync(0xffffffffu, m, s2));
    __syncthreads();                       // protect red[] WAR vs renorm reads
    if (lane == 0) red[wid] = m;
    __syncthreads();
    m = fmaxf(red[0], red[1]);

    float e = __expf(a - m);
    #pragma unroll
    for (int s2 = 16; s2 > 0; s2 >>= 1)
        e += __shfl_xor_sync(0xffffffffu, e, s2);
    __syncthreads();                       // protect red[] WAR vs max reads
    if (lane == 0) red[wid] = e;
    __syncthreads();

    if (j == 0) {
        const float E = red[0] + red[1];
        out[b] = Lacc + m + __logf(E);
    }
}

extern "C" void kernel_launch(void* const* d_in, const int* in_sizes, int n_in,
                              void* d_out, int out_size) {
    const float* log_trans = (const float*)d_in[0];
    const float* log_emit  = (const float*)d_in[1];
    // d_in[2] (log_pi) is a delta on state 0 by construction; handled analytically.
    const int*   obvs      = (const int*)d_in[3];
    float*       out       = (float*)d_out;

    const int T = in_sizes[3] / BB;

    build_emitT_kernel<<<(VV * NS + 255) / 256, 256>>>(log_emit);
    hmm_forward_kernel<<<BB, NS>>>(log_trans, obvs, out, T);
}

// round 5
// speedup vs baseline: 1.0519x; 1.0048x over previous
#include <cuda_runtime.h>

// HMM batched log-forward, scaled linear-domain formulation.
// B=128 sequences, S=65 states (state 0 = bookend, dropped from recursion),
// V=1024 observation vocab, T=8192 timesteps.
//
// Inputs (metadata order):
//   d_in[0] log_trans  [65*65]  float32
//   d_in[1] log_emit   [65*1024] float32
//   d_in[2] log_pi     [65]     float32 (delta on state 0; exploited analytically)
//   d_in[3] obvs       [128*8192] int32
// Output: float32 [128] log-evidence per sequence.

#define BB 128
#define SS 65
#define NS 64    // active states 1..64
#define VV 1024

// Transposed, exponentiated emission table: g_emitT[o*64 + j] = exp(log_emit[(j+1), o])
__device__ float g_emitT[VV * NS];

__global__ void build_emitT_kernel(const float* __restrict__ log_emit) {
    int idx = blockIdx.x * blockDim.x + threadIdx.x;
    if (idx >= VV * NS) return;
    int o = idx >> 6;        // observation symbol
    int j = idx & 63;        // active state index (state j+1)
    g_emitT[idx] = __expf(log_emit[(j + 1) * VV + o]);
}

__global__ __launch_bounds__(NS, 1) void hmm_forward_kernel(
    const float* __restrict__ log_trans,
    const int*   __restrict__ obvs,
    float*       __restrict__ out,
    int T)
{
    const int b = blockIdx.x;
    const int j = threadIdx.x;            // dest state j+1
    const int lane = j & 31;
    const int wid  = j >> 5;
    const int* __restrict__ orow = obvs + (long long)b * T;

    __shared__ float4 ubuf4[2][NS / 4];   // double-buffered scaled alpha vector
    __shared__ float  red[2];             // cross-warp reduction scratch

    // ---- Load transition column into registers (linear domain), once ----
    float Tcol[NS];
    #pragma unroll
    for (int i = 0; i < NS; i++)
        Tcol[i] = __expf(log_trans[(i + 1) * SS + (j + 1)]);

    // ---- t = 0: pi is a delta on state 0 -> u1[j] = exp(LT[0,j+1]) * em0[j] ----
    int o0 = orow[0];
    float v = __expf(log_trans[0 * SS + (j + 1)]) * g_emitT[o0 * NS + j];

    float Lacc = 0.f, Lc = 0.f;           // Kahan accumulator for sum of log Z

    // Prefetch pipeline: em_next = emission row for step t (at loop top),
    //                    onext   = obvs[t+1]
    float em_next = g_emitT[orow[1] * NS + j];
    int   onext   = orow[2];

    for (int t = 1; t < T; t++) {
        const int buf = t & 1;
        reinterpret_cast<float*>(ubuf4[buf])[j] = v;
        __syncthreads();

        const float em = em_next;
        // Prefetch next step's emission + obs (clamped indices keep loads valid)
        float em_p = g_emitT[onext * NS + j];
        int   on_p = orow[(t + 2 < T) ? (t + 2) : (T - 1)];

        // 64-wide dot: d_j = sum_i u_i * T[i][j], fully unrolled, 4 accumulators
        float acc0 = 0.f, acc1 = 0.f, acc2 = 0.f, acc3 = 0.f;
        const float4* __restrict__ u4 = ubuf4[buf];
        #pragma unroll
        for (int i = 0; i < NS / 4; i++) {
            float4 uu = u4[i];
            acc0 = fmaf(uu.x, Tcol[4 * i + 0], acc0);
            acc1 = fmaf(uu.y, Tcol[4 * i + 1], acc1);
            acc2 = fmaf(uu.z, Tcol[4 * i + 2], acc2);
            acc3 = fmaf(uu.w, Tcol[4 * i + 3], acc3);
        }
        v = ((acc0 + acc1) + (acc2 + acc3)) * em;

        em_next = em_p;
        onext   = on_p;

        // ---- Renormalize every 8 steps: u /= sum(u), Lacc += log(sum) ----
        if ((t & 7) == 7) {
            float z = v;
            #pragma unroll
            for (int s2 = 16; s2 > 0; s2 >>= 1)
                z += __shfl_xor_sync(0xffffffffu, z, s2);
            if (lane == 0) red[wid] = z;
            __syncthreads();
            const float Z = red[0] + red[1];
            v *= __frcp_rn(Z);
            const float lz = __logf(Z);
            // Kahan summation
            const float y = lz - Lc;
            const float s = Lacc + y;
            Lc = (s - Lacc) - y;
            Lacc = s;
        }
    }

    // ---- Termination: logL = Lacc + logsumexp_j( log(v_j) + LT[j+1, 0] ) ----
    const float lt0 = log_trans[(j + 1) * SS + 0];
    float a = (v > 0.f) ? (__logf(v) + lt0) : -3.0e38f;

    float m = a;
    #pragma unroll
    for (int s2 = 16; s2 > 0; s2 >>= 1)
        m = fmaxf(m, __shfl_xor_sync(0xffffffffu, m, s2));
    __syncthreads();                       // protect red[] WAR vs renorm reads
    if (lane == 0) red[wid] = m;
    __syncthreads();
    m = fmaxf(red[0], red[1]);

    float e = __expf(a - m);
    #pragma unroll
    for (int s2 = 16; s2 > 0; s2 >>= 1)
        e += __shfl_xor_sync(0xffffffffu, e, s2);
    __syncthreads();                       // protect red[] WAR vs max reads
    if (lane == 0) red[wid] = e;
    __syncthreads();

    if (j == 0) {
        const float E = red[0] + red[1];
        out[b] = Lacc + m + __logf(E);
    }
}

extern "C" void kernel_launch(void* const* d_in, const int* in_sizes, int n_in,
                              void* d_out, int out_size) {
    const float* log_trans = (const float*)d_in[0];
    const float* log_emit  = (const float*)d_in[1];
    // d_in[2] (log_pi) is a delta on state 0 by construction; handled analytically.
    const int*   obvs      = (const int*)d_in[3];
    float*       out       = (float*)d_out;

    const int T = in_sizes[3] / BB;

    build_emitT_kernel<<<(VV * NS + 255) / 256, 256>>>(log_emit);
    hmm_forward_kernel<<<BB, NS>>>(log_trans, obvs, out, T);
}